// round 15
// baseline (speedup 1.0000x reference)
#include <cuda_runtime.h>
#include <cstdint>

#define N_ 50000
#define E_ 800000

typedef unsigned long long ull;

// ---------------- scratch (device globals; no allocation) ----------------
__device__ __align__(16) float d_x   [N_*36];
__device__ __align__(16) float d_ea  [E_*16];
__device__ __align__(16) float d_eap [E_*16];   // ea permuted into CSR order
__device__ __align__(16) float d_agg [N_*128];
__device__ __align__(16) float d_h   [N_*128];
__device__ __align__(16) float d_h2  [N_*128];
__device__ __align__(16) float d_xl  [N_*128];
__device__ __align__(16) float d_xr  [N_*128];
__device__ __align__(16) float d_easum[16];
__device__ __align__(16) float d_eeL [128];
// CSR
__device__ int d_cnt   [N_];
__device__ int d_off   [N_ + 1];
__device__ int d_cursor[N_];
__device__ int d_asrc  [E_];
__device__ int d_tmp   [N_];
__device__ int d_bsum  [256];

// ---------------- helpers ----------------
__device__ __forceinline__ float lrelu(float x) { return x > 0.0f ? x : 0.2f * x; }

__device__ __forceinline__ ull pack2(float lo, float hi) {
    ull r; asm("mov.b64 %0, {%1, %2};" : "=l"(r) : "f"(lo), "f"(hi)); return r;
}
__device__ __forceinline__ void unpack2(ull v, float& lo, float& hi) {
    asm("mov.b64 {%0, %1}, %2;" : "=f"(lo), "=f"(hi) : "l"(v));
}
__device__ __forceinline__ ull fma2(ull a, ull b, ull c) {
    ull r; asm("fma.rn.f32x2 %0, %1, %2, %3;" : "=l"(r) : "l"(a), "l"(b), "l"(c)); return r;
}

#define FMA4(acc, s, wv) { acc.x += (s)*(wv).x; acc.y += (s)*(wv).y; acc.z += (s)*(wv).z; acc.w += (s)*(wv).w; }

// single-accumulator packed accumulate of one ea row against Wp
#define ACC1x16(A, g0, g1, g2, g3, Wp) { \
    ull sp; \
    sp = pack2(g0.x, g0.x); A = fma2(sp, Wp[0],  A); \
    sp = pack2(g0.y, g0.y); A = fma2(sp, Wp[1],  A); \
    sp = pack2(g0.z, g0.z); A = fma2(sp, Wp[2],  A); \
    sp = pack2(g0.w, g0.w); A = fma2(sp, Wp[3],  A); \
    sp = pack2(g1.x, g1.x); A = fma2(sp, Wp[4],  A); \
    sp = pack2(g1.y, g1.y); A = fma2(sp, Wp[5],  A); \
    sp = pack2(g1.z, g1.z); A = fma2(sp, Wp[6],  A); \
    sp = pack2(g1.w, g1.w); A = fma2(sp, Wp[7],  A); \
    sp = pack2(g2.x, g2.x); A = fma2(sp, Wp[8],  A); \
    sp = pack2(g2.y, g2.y); A = fma2(sp, Wp[9],  A); \
    sp = pack2(g2.z, g2.z); A = fma2(sp, Wp[10], A); \
    sp = pack2(g2.w, g2.w); A = fma2(sp, Wp[11], A); \
    sp = pack2(g3.x, g3.x); A = fma2(sp, Wp[12], A); \
    sp = pack2(g3.y, g3.y); A = fma2(sp, Wp[13], A); \
    sp = pack2(g3.z, g3.z); A = fma2(sp, Wp[14], A); \
    sp = pack2(g3.w, g3.w); A = fma2(sp, Wp[15], A); }

// dual-channel packed accumulate of one ea row (16 scalars) against Wp0/Wp1
#define ACC2x16(A0, A1, g0, g1, g2, g3) { \
    ull sp; \
    sp = pack2(g0.x, g0.x); A0 = fma2(sp, Wp0[0],  A0); A1 = fma2(sp, Wp1[0],  A1); \
    sp = pack2(g0.y, g0.y); A0 = fma2(sp, Wp0[1],  A0); A1 = fma2(sp, Wp1[1],  A1); \
    sp = pack2(g0.z, g0.z); A0 = fma2(sp, Wp0[2],  A0); A1 = fma2(sp, Wp1[2],  A1); \
    sp = pack2(g0.w, g0.w); A0 = fma2(sp, Wp0[3],  A0); A1 = fma2(sp, Wp1[3],  A1); \
    sp = pack2(g1.x, g1.x); A0 = fma2(sp, Wp0[4],  A0); A1 = fma2(sp, Wp1[4],  A1); \
    sp = pack2(g1.y, g1.y); A0 = fma2(sp, Wp0[5],  A0); A1 = fma2(sp, Wp1[5],  A1); \
    sp = pack2(g1.z, g1.z); A0 = fma2(sp, Wp0[6],  A0); A1 = fma2(sp, Wp1[6],  A1); \
    sp = pack2(g1.w, g1.w); A0 = fma2(sp, Wp0[7],  A0); A1 = fma2(sp, Wp1[7],  A1); \
    sp = pack2(g2.x, g2.x); A0 = fma2(sp, Wp0[8],  A0); A1 = fma2(sp, Wp1[8],  A1); \
    sp = pack2(g2.y, g2.y); A0 = fma2(sp, Wp0[9],  A0); A1 = fma2(sp, Wp1[9],  A1); \
    sp = pack2(g2.z, g2.z); A0 = fma2(sp, Wp0[10], A0); A1 = fma2(sp, Wp1[10], A1); \
    sp = pack2(g2.w, g2.w); A0 = fma2(sp, Wp0[11], A0); A1 = fma2(sp, Wp1[11], A1); \
    sp = pack2(g3.x, g3.x); A0 = fma2(sp, Wp0[12], A0); A1 = fma2(sp, Wp1[12], A1); \
    sp = pack2(g3.y, g3.y); A0 = fma2(sp, Wp0[13], A0); A1 = fma2(sp, Wp1[13], A1); \
    sp = pack2(g3.z, g3.z); A0 = fma2(sp, Wp0[14], A0); A1 = fma2(sp, Wp1[14], A1); \
    sp = pack2(g3.w, g3.w); A0 = fma2(sp, Wp0[15], A0); A1 = fma2(sp, Wp1[15], A1); }

// ---------------- feature assembly ----------------
__global__ void k_node_feat(const int* __restrict__ xcat, const float* __restrict__ xcont,
                            const float* __restrict__ emb) {
    int i = blockIdx.x * blockDim.x + threadIdx.x;
    if (i >= N_ * 36) return;
    int n = i / 36, j = i - n * 36;
    d_x[i] = (j < 20) ? emb[xcat[n] * 20 + j] : xcont[n * 16 + (j - 20)];
}

// edge features + folded easum block-reduction (E_*16 is an exact multiple of 256)
__global__ void k_edge_feat(const int* __restrict__ ecat, const float* __restrict__ econt,
                            const float* __restrict__ emb) {
    __shared__ float s[16];
    int t = threadIdx.x;
    int i = blockIdx.x * 256 + t;
    int e = i >> 4, j = i & 15;
    float v = (j < 4) ? emb[ecat[e] * 4 + j] : econt[e * 12 + (j - 4)];
    d_ea[i] = v;
    if (t < 16) s[t] = 0.0f;
    __syncthreads();
    atomicAdd(&s[j], v);
    __syncthreads();
    if (t < 16) atomicAdd(&d_easum[t], s[t]);
}

__global__ void k_eeloop(const float* __restrict__ We) {
    int c = threadIdx.x;
    float s = 0.0f;
#pragma unroll
    for (int k = 0; k < 16; k++) s += d_easum[k] * We[k * 128 + c];
    d_eeL[c] = s * (1.0f / (float)E_);
}

// ---------------- CSR build ----------------
__global__ void k_count(const int* __restrict__ dst) {
    int e = blockIdx.x * blockDim.x + threadIdx.x;
    if (e < E_) atomicAdd(&d_cnt[dst[e]], 1);
}

__global__ __launch_bounds__(256) void k_scan1() {
    int t = threadIdx.x, lane = t & 31, w = t >> 5;
    int idx = blockIdx.x * 256 + t;
    int v = (idx < N_) ? d_cnt[idx] : 0;
    int s = v;
#pragma unroll
    for (int o = 1; o < 32; o <<= 1) {
        int u = __shfl_up_sync(0xffffffffu, s, o);
        if (lane >= o) s += u;
    }
    __shared__ int wsum[8];
    if (lane == 31) wsum[w] = s;
    __syncthreads();
    if (t < 8) {
        int ws = wsum[t];
#pragma unroll
        for (int o = 1; o < 8; o <<= 1) {
            int u = __shfl_up_sync(0xffu, ws, o);
            if (t >= o) ws += u;
        }
        wsum[t] = ws;
    }
    __syncthreads();
    int incl = s + (w > 0 ? wsum[w - 1] : 0);
    if (idx < N_) d_tmp[idx] = incl - v;
    if (t == 255) d_bsum[blockIdx.x] = incl;
}

__global__ __launch_bounds__(256) void k_scan2() {
    int t = threadIdx.x, lane = t & 31, w = t >> 5;
    int v = (t < 196) ? d_bsum[t] : 0;
    int s = v;
#pragma unroll
    for (int o = 1; o < 32; o <<= 1) {
        int u = __shfl_up_sync(0xffffffffu, s, o);
        if (lane >= o) s += u;
    }
    __shared__ int wsum[8];
    if (lane == 31) wsum[w] = s;
    __syncthreads();
    if (t < 8) {
        int ws = wsum[t];
#pragma unroll
        for (int o = 1; o < 8; o <<= 1) {
            int u = __shfl_up_sync(0xffu, ws, o);
            if (t >= o) ws += u;
        }
        wsum[t] = ws;
    }
    __syncthreads();
    int excl = s + (w > 0 ? wsum[w - 1] : 0) - v;
    if (t < 196) d_bsum[t] = excl;
}

__global__ void k_scan3() {
    int idx = blockIdx.x * 256 + threadIdx.x;
    if (idx < N_) {
        int o = d_tmp[idx] + d_bsum[blockIdx.x];
        d_off[idx] = o;
        d_cursor[idx] = o;
    }
    if (idx == 0) d_off[N_] = E_;
}

// fill: permutes ea into CSR order (coalesced read, scattered 64B write)
__global__ void k_fill(const int* __restrict__ src, const int* __restrict__ dst) {
    int e = blockIdx.x * blockDim.x + threadIdx.x;
    if (e >= E_) return;
    int pos = atomicAdd(&d_cursor[dst[e]], 1);
    d_asrc[pos] = src[e];
    const float4* in = ((const float4*)d_ea) + (size_t)e * 4;
    float4* outp = ((float4*)d_eap) + (size_t)pos * 4;
    outp[0] = in[0]; outp[1] = in[1]; outp[2] = in[2]; outp[3] = in[3];
}

// ---------------- GINE1 (CSR): 2 warps per dst (edge-split), packed FMA2 ----------------
__global__ __launch_bounds__(256, 2) void k_gine1_csr(const float* __restrict__ W, const float* __restrict__ b) {
    __shared__ float s1[4][32];
    __shared__ float s2[4][32];
    int tid = threadIdx.x;
    int lane = tid & 31, w = tid >> 5;
    int gw = blockIdx.x * 8 + w;
    int n = gw >> 1, half = gw & 1, nl = w >> 1;
    ull Wp[16];
#pragma unroll
    for (int k = 0; k < 16; k++) Wp[k] = pack2(W[k * 36 + lane], W[k * 36 + 32 + (lane & 3)]);
    ull bp = pack2(b[lane], b[32 + (lane & 3)]);

    int js = d_off[n], je = d_off[n + 1];
    int mid = (js + je + 1) >> 1;
    int j = half ? mid : js;
    int jend = half ? je : mid;

    float acc1 = 0.0f, acc2 = 0.0f;
    for (; j + 1 < jend; j += 2) {
        int sA = d_asrc[j], sB = d_asrc[j + 1];
        const float4* p = ((const float4*)d_eap) + (size_t)j * 4;
        float4 a0 = p[0], a1 = p[1], a2 = p[2], a3 = p[3];
        float4 c0 = p[4], c1 = p[5], c2 = p[6], c3 = p[7];
        float xA1 = d_x[(size_t)sA * 36 + lane];
        float xA2 = d_x[(size_t)sA * 36 + 32 + (lane & 3)];
        float xB1 = d_x[(size_t)sB * 36 + lane];
        float xB2 = d_x[(size_t)sB * 36 + 32 + (lane & 3)];
        ull aA = bp, aB = bp;
        ACC1x16(aA, a0, a1, a2, a3, Wp);
        ACC1x16(aB, c0, c1, c2, c3, Wp);
        float r1, r2;
        unpack2(aA, r1, r2); acc1 += fmaxf(xA1 + r1, 0.0f); acc2 += fmaxf(xA2 + r2, 0.0f);
        unpack2(aB, r1, r2); acc1 += fmaxf(xB1 + r1, 0.0f); acc2 += fmaxf(xB2 + r2, 0.0f);
    }
    if (j < jend) {
        int sA = d_asrc[j];
        const float4* p = ((const float4*)d_eap) + (size_t)j * 4;
        float4 a0 = p[0], a1 = p[1], a2 = p[2], a3 = p[3];
        float xA1 = d_x[(size_t)sA * 36 + lane];
        float xA2 = d_x[(size_t)sA * 36 + 32 + (lane & 3)];
        ull aA = bp;
        ACC1x16(aA, a0, a1, a2, a3, Wp);
        float r1, r2;
        unpack2(aA, r1, r2);
        acc1 += fmaxf(xA1 + r1, 0.0f);
        acc2 += fmaxf(xA2 + r2, 0.0f);
    }
    if (half) { s1[nl][lane] = acc1; s2[nl][lane] = acc2; }
    __syncthreads();
    if (!half) {
        acc1 += s1[nl][lane];
        acc2 += s2[nl][lane];
        d_agg[(size_t)n * 36 + lane] = acc1;
        if (lane < 4) d_agg[(size_t)n * 36 + 32 + lane] = acc2;
    }
}

// ---------------- GINE2 (CSR): 2 warps per dst (edge-split), packed FMA2 ----------------
__global__ __launch_bounds__(256, 2) void k_gine2_csr(const float* __restrict__ W, const float* __restrict__ b) {
    __shared__ float4 sacc[4][32];
    int tid = threadIdx.x;
    int lane = tid & 31, w = tid >> 5;
    int gw = blockIdx.x * 8 + w;
    int n = gw >> 1, half = gw & 1, nl = w >> 1;
    ull Wp0[16], Wp1[16];
#pragma unroll
    for (int k = 0; k < 16; k++) {
        float4 wv = ((const float4*)W)[k * 32 + lane];
        Wp0[k] = pack2(wv.x, wv.y);
        Wp1[k] = pack2(wv.z, wv.w);
    }
    float4 bv = ((const float4*)b)[lane];
    ull bp0 = pack2(bv.x, bv.y), bp1 = pack2(bv.z, bv.w);

    int js = d_off[n], je = d_off[n + 1];
    int mid = (js + je + 1) >> 1;
    int j = half ? mid : js;
    int jend = half ? je : mid;

    float4 acc = make_float4(0, 0, 0, 0);
    for (; j + 1 < jend; j += 2) {
        int sA = d_asrc[j], sB = d_asrc[j + 1];
        const float4* p = ((const float4*)d_eap) + (size_t)j * 4;
        float4 a0 = p[0], a1 = p[1], a2 = p[2], a3 = p[3];
        float4 c0 = p[4], c1 = p[5], c2 = p[6], c3 = p[7];
        float4 hA = ((const float4*)d_h)[(size_t)sA * 32 + lane];
        float4 hB = ((const float4*)d_h)[(size_t)sB * 32 + lane];
        ull A0 = bp0, A1 = bp1;
        ACC2x16(A0, A1, a0, a1, a2, a3);
        ull B0 = bp0, B1 = bp1;
        ACC2x16(B0, B1, c0, c1, c2, c3);
        float rx, ry, rz, rw;
        unpack2(A0, rx, ry); unpack2(A1, rz, rw);
        acc.x += fmaxf(hA.x + rx, 0.0f); acc.y += fmaxf(hA.y + ry, 0.0f);
        acc.z += fmaxf(hA.z + rz, 0.0f); acc.w += fmaxf(hA.w + rw, 0.0f);
        unpack2(B0, rx, ry); unpack2(B1, rz, rw);
        acc.x += fmaxf(hB.x + rx, 0.0f); acc.y += fmaxf(hB.y + ry, 0.0f);
        acc.z += fmaxf(hB.z + rz, 0.0f); acc.w += fmaxf(hB.w + rw, 0.0f);
    }
    if (j < jend) {
        int sA = d_asrc[j];
        const float4* p = ((const float4*)d_eap) + (size_t)j * 4;
        float4 a0 = p[0], a1 = p[1], a2 = p[2], a3 = p[3];
        float4 hA = ((const float4*)d_h)[(size_t)sA * 32 + lane];
        ull A0 = bp0, A1 = bp1;
        ACC2x16(A0, A1, a0, a1, a2, a3);
        float rx, ry, rz, rw;
        unpack2(A0, rx, ry); unpack2(A1, rz, rw);
        acc.x += fmaxf(hA.x + rx, 0.0f); acc.y += fmaxf(hA.y + ry, 0.0f);
        acc.z += fmaxf(hA.z + rz, 0.0f); acc.w += fmaxf(hA.w + rw, 0.0f);
    }
    if (half) sacc[nl][lane] = acc;
    __syncthreads();
    if (!half) {
        float4 o = sacc[nl][lane];
        acc.x += o.x; acc.y += o.y; acc.z += o.z; acc.w += o.w;
        ((float4*)d_agg)[(size_t)n * 32 + lane] = acc;
    }
}

// ---------------- node MLP: 4 rows/thread, k-blocked x4, float4 staging ----------------
template <int K, bool HASAGG, bool HASBN>
__global__ __launch_bounds__(256) void k_mlp(
    const float* __restrict__ xin, const float* __restrict__ agg,
    const float* __restrict__ epsp,
    const float* __restrict__ W, const float* __restrict__ bias,
    const float* __restrict__ bng, const float* __restrict__ bnb,
    const float* __restrict__ bnm, const float* __restrict__ bnv,
    float* __restrict__ out)
{
    constexpr int TS = (K == 36) ? 40 : K;
    constexpr int K4 = K / 4;
    extern __shared__ float sm[];
    float* Ws  = sm;             // K*128
    float* tin = sm + K * 128;   // 32*TS
    int tid = threadIdx.x;
    int lane = tid & 31, w = tid >> 5;
    for (int i = tid; i < K * 32; i += 256) ((float4*)Ws)[i] = ((const float4*)W)[i];
    int c = lane * 4;
    float4 bv = *(const float4*)(bias + c);
    float4 scale = make_float4(1,1,1,1), shift = make_float4(0,0,0,0);
    if (HASBN) {
        float s0 = bng[c+0] * rsqrtf(bnv[c+0] + 1e-5f);
        float s1 = bng[c+1] * rsqrtf(bnv[c+1] + 1e-5f);
        float s2 = bng[c+2] * rsqrtf(bnv[c+2] + 1e-5f);
        float s3 = bng[c+3] * rsqrtf(bnv[c+3] + 1e-5f);
        scale = make_float4(s0, s1, s2, s3);
        shift = make_float4(bnb[c+0] - bnm[c+0]*s0, bnb[c+1] - bnm[c+1]*s1,
                            bnb[c+2] - bnm[c+2]*s2, bnb[c+3] - bnm[c+3]*s3);
    }
    float sx = HASAGG ? (1.0f + *epsp) : 1.0f;
    __syncthreads();

    for (int base = blockIdx.x * 32; base < N_; base += gridDim.x * 32) {
        for (int i = tid; i < 32 * K4; i += 256) {
            int r = i / K4, k4 = i - r * K4;
            int n = base + r;
            if (n < N_) {
                float4 v = *(const float4*)(xin + (size_t)n * K + k4 * 4);
                v.x *= sx; v.y *= sx; v.z *= sx; v.w *= sx;
                if (HASAGG) {
                    float4 g = *(const float4*)(agg + (size_t)n * K + k4 * 4);
                    v.x += g.x; v.y += g.y; v.z += g.z; v.w += g.w;
                }
                *(float4*)(tin + r * TS + k4 * 4) = v;
            }
        }
        __syncthreads();
        const float* t0 = tin + (w * 4) * TS;
        float4 a0 = bv, a1 = bv, a2 = bv, a3 = bv;
#pragma unroll
        for (int k4 = 0; k4 < K; k4 += 4) {
            float4 w0 = *(const float4*)(Ws + (k4+0) * 128 + c);
            float4 w1 = *(const float4*)(Ws + (k4+1) * 128 + c);
            float4 w2 = *(const float4*)(Ws + (k4+2) * 128 + c);
            float4 w3 = *(const float4*)(Ws + (k4+3) * 128 + c);
            float4 t;
            t = *(const float4*)(t0 + 0 * TS + k4);
            FMA4(a0, t.x, w0); FMA4(a0, t.y, w1); FMA4(a0, t.z, w2); FMA4(a0, t.w, w3);
            t = *(const float4*)(t0 + 1 * TS + k4);
            FMA4(a1, t.x, w0); FMA4(a1, t.y, w1); FMA4(a1, t.z, w2); FMA4(a1, t.w, w3);
            t = *(const float4*)(t0 + 2 * TS + k4);
            FMA4(a2, t.x, w0); FMA4(a2, t.y, w1); FMA4(a2, t.z, w2); FMA4(a2, t.w, w3);
            t = *(const float4*)(t0 + 3 * TS + k4);
            FMA4(a3, t.x, w0); FMA4(a3, t.y, w1); FMA4(a3, t.z, w2); FMA4(a3, t.w, w3);
        }
        if (HASBN) {
            a0.x = fmaxf(a0.x,0.f)*scale.x+shift.x; a0.y = fmaxf(a0.y,0.f)*scale.y+shift.y;
            a0.z = fmaxf(a0.z,0.f)*scale.z+shift.z; a0.w = fmaxf(a0.w,0.f)*scale.w+shift.w;
            a1.x = fmaxf(a1.x,0.f)*scale.x+shift.x; a1.y = fmaxf(a1.y,0.f)*scale.y+shift.y;
            a1.z = fmaxf(a1.z,0.f)*scale.z+shift.z; a1.w = fmaxf(a1.w,0.f)*scale.w+shift.w;
            a2.x = fmaxf(a2.x,0.f)*scale.x+shift.x; a2.y = fmaxf(a2.y,0.f)*scale.y+shift.y;
            a2.z = fmaxf(a2.z,0.f)*scale.z+shift.z; a2.w = fmaxf(a2.w,0.f)*scale.w+shift.w;
            a3.x = fmaxf(a3.x,0.f)*scale.x+shift.x; a3.y = fmaxf(a3.y,0.f)*scale.y+shift.y;
            a3.z = fmaxf(a3.z,0.f)*scale.z+shift.z; a3.w = fmaxf(a3.w,0.f)*scale.w+shift.w;
        }
        int n0 = base + w * 4;
        if (n0 + 0 < N_) *(float4*)(out + (size_t)(n0+0) * 128 + c) = a0;
        if (n0 + 1 < N_) *(float4*)(out + (size_t)(n0+1) * 128 + c) = a1;
        if (n0 + 2 < N_) *(float4*)(out + (size_t)(n0+2) * 128 + c) = a2;
        if (n0 + 3 < N_) *(float4*)(out + (size_t)(n0+3) * 128 + c) = a3;
        __syncthreads();
    }
}

// ---------------- GATv2 (CSR): 2 warps per dst (edge-split), fused softmax ----------------
__global__ __launch_bounds__(256, 2) void k_gat_csr(const float* __restrict__ Wg, const float* __restrict__ attv,
                                                    const float* __restrict__ bias, float* __restrict__ out) {
    __shared__ float4 sacc[4][32];
    __shared__ float  sden[4][32];
    int tid = threadIdx.x;
    int lane = tid & 31, w = tid >> 5;
    int gw = blockIdx.x * 8 + w;
    int n = gw >> 1, half = gw & 1, nl = w >> 1;
    ull Wp0[16], Wp1[16];
#pragma unroll
    for (int k = 0; k < 16; k++) {
        float4 wv = ((const float4*)Wg)[k * 32 + lane];
        Wp0[k] = pack2(wv.x, wv.y);
        Wp1[k] = pack2(wv.z, wv.w);
    }
    float4 av = ((const float4*)attv)[lane];
    float4 xr_d = ((const float4*)d_xr)[(size_t)n * 32 + lane];

    int js = d_off[n], je = d_off[n + 1];
    int mid = (js + je + 1) >> 1;
    int j = half ? mid : js;
    int jend = half ? je : mid;

    float4 acc = make_float4(0, 0, 0, 0);
    float den = 0.0f;
    for (; j + 1 < jend; j += 2) {
        int sA = d_asrc[j], sB = d_asrc[j + 1];
        const float4* p = ((const float4*)d_eap) + (size_t)j * 4;
        float4 a0 = p[0], a1 = p[1], a2 = p[2], a3 = p[3];
        float4 c0 = p[4], c1 = p[5], c2 = p[6], c3 = p[7];
        float4 xlA = ((const float4*)d_xl)[(size_t)sA * 32 + lane];
        float4 xlB = ((const float4*)d_xl)[(size_t)sB * 32 + lane];
        ull A0 = 0, A1 = 0;
        ACC2x16(A0, A1, a0, a1, a2, a3);
        ull B0 = 0, B1 = 0;
        ACC2x16(B0, B1, c0, c1, c2, c3);
        float rx, ry, rz, rw;
        unpack2(A0, rx, ry); unpack2(A1, rz, rw);
        float qA = lrelu(xlA.x + xr_d.x + rx) * av.x
                 + lrelu(xlA.y + xr_d.y + ry) * av.y
                 + lrelu(xlA.z + xr_d.z + rz) * av.z
                 + lrelu(xlA.w + xr_d.w + rw) * av.w;
        unpack2(B0, rx, ry); unpack2(B1, rz, rw);
        float qB = lrelu(xlB.x + xr_d.x + rx) * av.x
                 + lrelu(xlB.y + xr_d.y + ry) * av.y
                 + lrelu(xlB.z + xr_d.z + rz) * av.z
                 + lrelu(xlB.w + xr_d.w + rw) * av.w;
        qA += __shfl_xor_sync(0xffffffffu, qA, 1);
        qB += __shfl_xor_sync(0xffffffffu, qB, 1);
        qA += __shfl_xor_sync(0xffffffffu, qA, 2);
        qB += __shfl_xor_sync(0xffffffffu, qB, 2);
        qA += __shfl_xor_sync(0xffffffffu, qA, 4);
        qB += __shfl_xor_sync(0xffffffffu, qB, 4);
        qA += __shfl_xor_sync(0xffffffffu, qA, 8);
        qB += __shfl_xor_sync(0xffffffffu, qB, 8);
        float exA = __expf(qA), exB = __expf(qB);
        acc.x += exA * xlA.x + exB * xlB.x;
        acc.y += exA * xlA.y + exB * xlB.y;
        acc.z += exA * xlA.z + exB * xlB.z;
        acc.w += exA * xlA.w + exB * xlB.w;
        den += exA + exB;
    }
    if (j < jend) {
        int sA = d_asrc[j];
        const float4* p = ((const float4*)d_eap) + (size_t)j * 4;
        float4 a0 = p[0], a1 = p[1], a2 = p[2], a3 = p[3];
        float4 xlA = ((const float4*)d_xl)[(size_t)sA * 32 + lane];
        ull A0 = 0, A1 = 0;
        ACC2x16(A0, A1, a0, a1, a2, a3);
        float rx, ry, rz, rw;
        unpack2(A0, rx, ry); unpack2(A1, rz, rw);
        float qA = lrelu(xlA.x + xr_d.x + rx) * av.x
                 + lrelu(xlA.y + xr_d.y + ry) * av.y
                 + lrelu(xlA.z + xr_d.z + rz) * av.z
                 + lrelu(xlA.w + xr_d.w + rw) * av.w;
        qA += __shfl_xor_sync(0xffffffffu, qA, 1);
        qA += __shfl_xor_sync(0xffffffffu, qA, 2);
        qA += __shfl_xor_sync(0xffffffffu, qA, 4);
        qA += __shfl_xor_sync(0xffffffffu, qA, 8);
        float exA = __expf(qA);
        acc.x += exA * xlA.x; acc.y += exA * xlA.y;
        acc.z += exA * xlA.z; acc.w += exA * xlA.w;
        den += exA;
    }

    if (half) { sacc[nl][lane] = acc; sden[nl][lane] = den; }
    __syncthreads();
    if (!half) {
        float4 o = sacc[nl][lane];
        acc.x += o.x; acc.y += o.y; acc.z += o.z; acc.w += o.w;
        den += sden[nl][lane];

        // self-loop (edge attr = mean of ea -> eeL)
        float4 xl_d = ((const float4*)d_xl)[(size_t)n * 32 + lane];
        float4 eeL  = ((const float4*)d_eeL)[lane];
        float q = lrelu(xl_d.x + xr_d.x + eeL.x) * av.x
                + lrelu(xl_d.y + xr_d.y + eeL.y) * av.y
                + lrelu(xl_d.z + xr_d.z + eeL.z) * av.z
                + lrelu(xl_d.w + xr_d.w + eeL.w) * av.w;
        q += __shfl_xor_sync(0xffffffffu, q, 1);
        q += __shfl_xor_sync(0xffffffffu, q, 2);
        q += __shfl_xor_sync(0xffffffffu, q, 4);
        q += __shfl_xor_sync(0xffffffffu, q, 8);
        float ex = __expf(q);
        acc.x += ex * xl_d.x; acc.y += ex * xl_d.y;
        acc.z += ex * xl_d.z; acc.w += ex * xl_d.w;
        den += ex;

        // head mean: lanes 0-15 hold head0 channels, lanes 16-31 hold head1
        float4 accP;
        accP.x = __shfl_xor_sync(0xffffffffu, acc.x, 16);
        accP.y = __shfl_xor_sync(0xffffffffu, acc.y, 16);
        accP.z = __shfl_xor_sync(0xffffffffu, acc.z, 16);
        accP.w = __shfl_xor_sync(0xffffffffu, acc.w, 16);
        float denP = __shfl_xor_sync(0xffffffffu, den, 16);
        if (lane < 16) {
            float4 bias4 = ((const float4*)bias)[lane];
            float inv = 0.5f / den, invP = 0.5f / denP;
            float4 o2;
            o2.x = acc.x * inv + accP.x * invP + bias4.x;
            o2.y = acc.y * inv + accP.y * invP + bias4.y;
            o2.z = acc.z * inv + accP.z * invP + bias4.z;
            o2.w = acc.w * inv + accP.w * invP + bias4.w;
            ((float4*)out)[(size_t)n * 16 + lane] = o2;
        }
    }
}

// ---------------- launch ----------------
extern "C" void kernel_launch(void* const* d_in, const int* in_sizes, int n_in,
                              void* d_out, int out_size) {
    const int*   x_cat    = (const int*)  d_in[0];
    const float* x_cont   = (const float*)d_in[1];
    const int*   e_cat    = (const int*)  d_in[2];
    const float* e_cont   = (const float*)d_in[3];
    const int*   eidx     = (const int*)  d_in[4];
    const int*   src = eidx;
    const int*   dst = eidx + E_;
    const float* node_emb = (const float*)d_in[5];
    const float* edge_emb = (const float*)d_in[6];
    const float* eps1     = (const float*)d_in[7];
    const float* W1e      = (const float*)d_in[8];
    const float* b1e      = (const float*)d_in[9];
    const float* nnW1     = (const float*)d_in[10];
    const float* nnb1     = (const float*)d_in[11];
    const float* g1 = (const float*)d_in[12], *bb1 = (const float*)d_in[13];
    const float* m1 = (const float*)d_in[14], *v1  = (const float*)d_in[15];
    const float* eps2     = (const float*)d_in[16];
    const float* W2e      = (const float*)d_in[17];
    const float* b2e      = (const float*)d_in[18];
    const float* nnW2     = (const float*)d_in[19];
    const float* nnb2     = (const float*)d_in[20];
    const float* g2 = (const float*)d_in[21], *bb2 = (const float*)d_in[22];
    const float* m2 = (const float*)d_in[23], *v2  = (const float*)d_in[24];
    const float* Wl  = (const float*)d_in[25], *bl = (const float*)d_in[26];
    const float* Wr  = (const float*)d_in[27], *br = (const float*)d_in[28];
    const float* Weg = (const float*)d_in[29];
    const float* att = (const float*)d_in[30];
    const float* gbias = (const float*)d_in[31];
    float* out = (float*)d_out;

    void *p_x, *p_agg, *p_h, *p_h2, *p_xl, *p_xr, *p_easum, *p_cnt;
    cudaGetSymbolAddress(&p_x,    d_x);
    cudaGetSymbolAddress(&p_agg,  d_agg);
    cudaGetSymbolAddress(&p_h,    d_h);
    cudaGetSymbolAddress(&p_h2,   d_h2);
    cudaGetSymbolAddress(&p_xl,   d_xl);
    cudaGetSymbolAddress(&p_xr,   d_xr);
    cudaGetSymbolAddress(&p_easum,d_easum);
    cudaGetSymbolAddress(&p_cnt,  d_cnt);

    const int smem36  = (36 * 128 + 32 * 40) * 4;    // 23552
    const int smem128 = (128 * 128 + 32 * 128) * 4;  // 81920
    cudaFuncSetAttribute(k_mlp<128, true,  true >, cudaFuncAttributeMaxDynamicSharedMemorySize, smem128);
    cudaFuncSetAttribute(k_mlp<128, false, false>, cudaFuncAttributeMaxDynamicSharedMemorySize, smem128);

    // init
    cudaMemsetAsync(p_easum, 0, 16 * 4);
    cudaMemsetAsync(p_cnt,   0, N_ * 4);

    // features (+folded easum)
    k_node_feat<<<(N_ * 36 + 255) / 256, 256>>>(x_cat, x_cont, node_emb);
    k_edge_feat<<<(E_ * 16) / 256, 256>>>(e_cat, e_cont, edge_emb);
    k_eeloop<<<1, 128>>>(Weg);

    // CSR build: count -> 3-phase parallel scan -> fill (permutes ea)
    const int nScanBlocks = (N_ + 255) / 256;   // 196
    k_count<<<(E_ + 255) / 256, 256>>>(dst);
    k_scan1<<<nScanBlocks, 256>>>();
    k_scan2<<<1, 256>>>();
    k_scan3<<<nScanBlocks, 256>>>();
    k_fill<<<(E_ + 255) / 256, 256>>>(src, dst);

    const int pairGrid = (N_ * 2) / 8;   // 2 warps per node, 8 warps/block = 12500 (exact)

    // GINE layer 1
    k_gine1_csr<<<pairGrid, 256>>>(W1e, b1e);
    k_mlp<36, true, true><<<296, 256, smem36>>>(
        (const float*)p_x, (const float*)p_agg, eps1, nnW1, nnb1, g1, bb1, m1, v1, (float*)p_h);

    // GINE layer 2
    k_gine2_csr<<<pairGrid, 256>>>(W2e, b2e);
    k_mlp<128, true, true><<<296, 256, smem128>>>(
        (const float*)p_h, (const float*)p_agg, eps2, nnW2, nnb2, g2, bb2, m2, v2, (float*)p_h2);

    // GATv2 linear transforms
    k_mlp<128, false, false><<<296, 256, smem128>>>(
        (const float*)p_h2, nullptr, nullptr, Wl, bl, nullptr, nullptr, nullptr, nullptr, (float*)p_xl);
    k_mlp<128, false, false><<<296, 256, smem128>>>(
        (const float*)p_h2, nullptr, nullptr, Wr, br, nullptr, nullptr, nullptr, nullptr, (float*)p_xr);

    // GATv2 fused attention + output
    k_gat_csr<<<pairGrid, 256>>>(Weg, att, gbias, out);
}

// round 16
// speedup vs baseline: 1.0508x; 1.0508x over previous
#include <cuda_runtime.h>
#include <cstdint>

#define N_ 50000
#define E_ 800000

typedef unsigned long long ull;

// ---------------- scratch (device globals; no allocation) ----------------
__device__ __align__(16) float d_x   [N_*36];
__device__ __align__(16) float d_ea  [E_*16];
__device__ __align__(16) float d_eap [E_*16];   // ea permuted into CSR order
__device__ __align__(16) float d_agg [N_*128];
__device__ __align__(16) float d_h   [N_*128];
__device__ __align__(16) float d_h2  [N_*128];
__device__ __align__(16) float d_xl  [N_*128];
__device__ __align__(16) float d_xr  [N_*128];
__device__ __align__(16) float d_easum[16];
__device__ __align__(16) float d_eeL [128];
// CSR
__device__ int d_cnt   [N_];
__device__ int d_off   [N_ + 1];
__device__ int d_cursor[N_];
__device__ int d_asrc  [E_];
__device__ int d_tmp   [N_];
__device__ int d_bsum  [256];

// ---------------- helpers ----------------
__device__ __forceinline__ float lrelu(float x) { return x > 0.0f ? x : 0.2f * x; }

__device__ __forceinline__ ull pack2(float lo, float hi) {
    ull r; asm("mov.b64 %0, {%1, %2};" : "=l"(r) : "f"(lo), "f"(hi)); return r;
}
__device__ __forceinline__ void unpack2(ull v, float& lo, float& hi) {
    asm("mov.b64 {%0, %1}, %2;" : "=f"(lo), "=f"(hi) : "l"(v));
}
__device__ __forceinline__ ull fma2(ull a, ull b, ull c) {
    ull r; asm("fma.rn.f32x2 %0, %1, %2, %3;" : "=l"(r) : "l"(a), "l"(b), "l"(c)); return r;
}

#define FMA4(acc, s, wv) { acc.x += (s)*(wv).x; acc.y += (s)*(wv).y; acc.z += (s)*(wv).z; acc.w += (s)*(wv).w; }

// dual-channel packed accumulate of one ea row (16 scalars) against Wp0/Wp1
#define ACC2x16(A0, A1, g0, g1, g2, g3) { \
    ull sp; \
    sp = pack2(g0.x, g0.x); A0 = fma2(sp, Wp0[0],  A0); A1 = fma2(sp, Wp1[0],  A1); \
    sp = pack2(g0.y, g0.y); A0 = fma2(sp, Wp0[1],  A0); A1 = fma2(sp, Wp1[1],  A1); \
    sp = pack2(g0.z, g0.z); A0 = fma2(sp, Wp0[2],  A0); A1 = fma2(sp, Wp1[2],  A1); \
    sp = pack2(g0.w, g0.w); A0 = fma2(sp, Wp0[3],  A0); A1 = fma2(sp, Wp1[3],  A1); \
    sp = pack2(g1.x, g1.x); A0 = fma2(sp, Wp0[4],  A0); A1 = fma2(sp, Wp1[4],  A1); \
    sp = pack2(g1.y, g1.y); A0 = fma2(sp, Wp0[5],  A0); A1 = fma2(sp, Wp1[5],  A1); \
    sp = pack2(g1.z, g1.z); A0 = fma2(sp, Wp0[6],  A0); A1 = fma2(sp, Wp1[6],  A1); \
    sp = pack2(g1.w, g1.w); A0 = fma2(sp, Wp0[7],  A0); A1 = fma2(sp, Wp1[7],  A1); \
    sp = pack2(g2.x, g2.x); A0 = fma2(sp, Wp0[8],  A0); A1 = fma2(sp, Wp1[8],  A1); \
    sp = pack2(g2.y, g2.y); A0 = fma2(sp, Wp0[9],  A0); A1 = fma2(sp, Wp1[9],  A1); \
    sp = pack2(g2.z, g2.z); A0 = fma2(sp, Wp0[10], A0); A1 = fma2(sp, Wp1[10], A1); \
    sp = pack2(g2.w, g2.w); A0 = fma2(sp, Wp0[11], A0); A1 = fma2(sp, Wp1[11], A1); \
    sp = pack2(g3.x, g3.x); A0 = fma2(sp, Wp0[12], A0); A1 = fma2(sp, Wp1[12], A1); \
    sp = pack2(g3.y, g3.y); A0 = fma2(sp, Wp0[13], A0); A1 = fma2(sp, Wp1[13], A1); \
    sp = pack2(g3.z, g3.z); A0 = fma2(sp, Wp0[14], A0); A1 = fma2(sp, Wp1[14], A1); \
    sp = pack2(g3.w, g3.w); A0 = fma2(sp, Wp0[15], A0); A1 = fma2(sp, Wp1[15], A1); }

// ---------------- feature assembly ----------------
__global__ void k_node_feat(const int* __restrict__ xcat, const float* __restrict__ xcont,
                            const float* __restrict__ emb) {
    int i = blockIdx.x * blockDim.x + threadIdx.x;
    if (i >= N_ * 36) return;
    int n = i / 36, j = i - n * 36;
    d_x[i] = (j < 20) ? emb[xcat[n] * 20 + j] : xcont[n * 16 + (j - 20)];
}

// edge features + folded easum block-reduction (E_*16 is an exact multiple of 256)
__global__ void k_edge_feat(const int* __restrict__ ecat, const float* __restrict__ econt,
                            const float* __restrict__ emb) {
    __shared__ float s[16];
    int t = threadIdx.x;
    int i = blockIdx.x * 256 + t;
    int e = i >> 4, j = i & 15;
    float v = (j < 4) ? emb[ecat[e] * 4 + j] : econt[e * 12 + (j - 4)];
    d_ea[i] = v;
    if (t < 16) s[t] = 0.0f;
    __syncthreads();
    atomicAdd(&s[j], v);
    __syncthreads();
    if (t < 16) atomicAdd(&d_easum[t], s[t]);
}

__global__ void k_eeloop(const float* __restrict__ We) {
    int c = threadIdx.x;
    float s = 0.0f;
#pragma unroll
    for (int k = 0; k < 16; k++) s += d_easum[k] * We[k * 128 + c];
    d_eeL[c] = s * (1.0f / (float)E_);
}

// ---------------- CSR build ----------------
__global__ void k_count(const int* __restrict__ dst) {
    int e = blockIdx.x * blockDim.x + threadIdx.x;
    if (e < E_) atomicAdd(&d_cnt[dst[e]], 1);
}

// phase 1: per-block (256 elems) exclusive scan + block sums  (grid = 196)
__global__ __launch_bounds__(256) void k_scan1() {
    int t = threadIdx.x, lane = t & 31, w = t >> 5;
    int idx = blockIdx.x * 256 + t;
    int v = (idx < N_) ? d_cnt[idx] : 0;
    int s = v;
#pragma unroll
    for (int o = 1; o < 32; o <<= 1) {
        int u = __shfl_up_sync(0xffffffffu, s, o);
        if (lane >= o) s += u;
    }
    __shared__ int wsum[8];
    if (lane == 31) wsum[w] = s;
    __syncthreads();
    if (t < 8) {
        int ws = wsum[t];
#pragma unroll
        for (int o = 1; o < 8; o <<= 1) {
            int u = __shfl_up_sync(0xffu, ws, o);
            if (t >= o) ws += u;
        }
        wsum[t] = ws;
    }
    __syncthreads();
    int incl = s + (w > 0 ? wsum[w - 1] : 0);
    if (idx < N_) d_tmp[idx] = incl - v;
    if (t == 255) d_bsum[blockIdx.x] = incl;
}

// phase 2: scan 196 block sums (1 block, 256 threads)
__global__ __launch_bounds__(256) void k_scan2() {
    int t = threadIdx.x, lane = t & 31, w = t >> 5;
    int v = (t < 196) ? d_bsum[t] : 0;
    int s = v;
#pragma unroll
    for (int o = 1; o < 32; o <<= 1) {
        int u = __shfl_up_sync(0xffffffffu, s, o);
        if (lane >= o) s += u;
    }
    __shared__ int wsum[8];
    if (lane == 31) wsum[w] = s;
    __syncthreads();
    if (t < 8) {
        int ws = wsum[t];
#pragma unroll
        for (int o = 1; o < 8; o <<= 1) {
            int u = __shfl_up_sync(0xffu, ws, o);
            if (t >= o) ws += u;
        }
        wsum[t] = ws;
    }
    __syncthreads();
    int excl = s + (w > 0 ? wsum[w - 1] : 0) - v;
    if (t < 196) d_bsum[t] = excl;
}

// phase 3: add block offsets, write off + cursor
__global__ void k_scan3() {
    int idx = blockIdx.x * 256 + threadIdx.x;
    if (idx < N_) {
        int o = d_tmp[idx] + d_bsum[blockIdx.x];
        d_off[idx] = o;
        d_cursor[idx] = o;
    }
    if (idx == 0) d_off[N_] = E_;
}

// fill: permutes ea into CSR order (coalesced read, scattered 64B write)
__global__ void k_fill(const int* __restrict__ src, const int* __restrict__ dst) {
    int e = blockIdx.x * blockDim.x + threadIdx.x;
    if (e >= E_) return;
    int pos = atomicAdd(&d_cursor[dst[e]], 1);
    d_asrc[pos] = src[e];
    const float4* in = ((const float4*)d_ea) + (size_t)e * 4;
    float4* outp = ((float4*)d_eap) + (size_t)pos * 4;
    outp[0] = in[0]; outp[1] = in[1]; outp[2] = in[2]; outp[3] = in[3];
}

// ---------------- GINE1 (CSR): warp per dst, 2-edge unroll, packed FMA2 ----------------
__global__ __launch_bounds__(256, 2) void k_gine1_csr(const float* __restrict__ W, const float* __restrict__ b) {
    int lane = threadIdx.x & 31;
    int n = (blockIdx.x * 256 + threadIdx.x) >> 5;
    if (n >= N_) return;
    ull Wp[16];
#pragma unroll
    for (int k = 0; k < 16; k++) Wp[k] = pack2(W[k * 36 + lane], W[k * 36 + 32 + (lane & 3)]);
    ull bp = pack2(b[lane], b[32 + (lane & 3)]);

    float acc1 = 0.0f, acc2 = 0.0f;
    int j = d_off[n], jend = d_off[n + 1];
    for (; j + 1 < jend; j += 2) {
        int sA = d_asrc[j], sB = d_asrc[j + 1];
        const float4* p = ((const float4*)d_eap) + (size_t)j * 4;
        float4 a0 = p[0], a1 = p[1], a2 = p[2], a3 = p[3];
        float4 c0 = p[4], c1 = p[5], c2 = p[6], c3 = p[7];
        float xA1 = d_x[(size_t)sA * 36 + lane];
        float xA2 = d_x[(size_t)sA * 36 + 32 + (lane & 3)];
        float xB1 = d_x[(size_t)sB * 36 + lane];
        float xB2 = d_x[(size_t)sB * 36 + 32 + (lane & 3)];
        ull aA = bp, aB = bp;
        ull sp;
        sp = pack2(a0.x, a0.x); aA = fma2(sp, Wp[0],  aA);  sp = pack2(c0.x, c0.x); aB = fma2(sp, Wp[0],  aB);
        sp = pack2(a0.y, a0.y); aA = fma2(sp, Wp[1],  aA);  sp = pack2(c0.y, c0.y); aB = fma2(sp, Wp[1],  aB);
        sp = pack2(a0.z, a0.z); aA = fma2(sp, Wp[2],  aA);  sp = pack2(c0.z, c0.z); aB = fma2(sp, Wp[2],  aB);
        sp = pack2(a0.w, a0.w); aA = fma2(sp, Wp[3],  aA);  sp = pack2(c0.w, c0.w); aB = fma2(sp, Wp[3],  aB);
        sp = pack2(a1.x, a1.x); aA = fma2(sp, Wp[4],  aA);  sp = pack2(c1.x, c1.x); aB = fma2(sp, Wp[4],  aB);
        sp = pack2(a1.y, a1.y); aA = fma2(sp, Wp[5],  aA);  sp = pack2(c1.y, c1.y); aB = fma2(sp, Wp[5],  aB);
        sp = pack2(a1.z, a1.z); aA = fma2(sp, Wp[6],  aA);  sp = pack2(c1.z, c1.z); aB = fma2(sp, Wp[6],  aB);
        sp = pack2(a1.w, a1.w); aA = fma2(sp, Wp[7],  aA);  sp = pack2(c1.w, c1.w); aB = fma2(sp, Wp[7],  aB);
        sp = pack2(a2.x, a2.x); aA = fma2(sp, Wp[8],  aA);  sp = pack2(c2.x, c2.x); aB = fma2(sp, Wp[8],  aB);
        sp = pack2(a2.y, a2.y); aA = fma2(sp, Wp[9],  aA);  sp = pack2(c2.y, c2.y); aB = fma2(sp, Wp[9],  aB);
        sp = pack2(a2.z, a2.z); aA = fma2(sp, Wp[10], aA);  sp = pack2(c2.z, c2.z); aB = fma2(sp, Wp[10], aB);
        sp = pack2(a2.w, a2.w); aA = fma2(sp, Wp[11], aA);  sp = pack2(c2.w, c2.w); aB = fma2(sp, Wp[11], aB);
        sp = pack2(a3.x, a3.x); aA = fma2(sp, Wp[12], aA);  sp = pack2(c3.x, c3.x); aB = fma2(sp, Wp[12], aB);
        sp = pack2(a3.y, a3.y); aA = fma2(sp, Wp[13], aA);  sp = pack2(c3.y, c3.y); aB = fma2(sp, Wp[13], aB);
        sp = pack2(a3.z, a3.z); aA = fma2(sp, Wp[14], aA);  sp = pack2(c3.z, c3.z); aB = fma2(sp, Wp[14], aB);
        sp = pack2(a3.w, a3.w); aA = fma2(sp, Wp[15], aA);  sp = pack2(c3.w, c3.w); aB = fma2(sp, Wp[15], aB);
        float rA1, rA2, rB1, rB2;
        unpack2(aA, rA1, rA2);
        unpack2(aB, rB1, rB2);
        acc1 += fmaxf(xA1 + rA1, 0.0f) + fmaxf(xB1 + rB1, 0.0f);
        acc2 += fmaxf(xA2 + rA2, 0.0f) + fmaxf(xB2 + rB2, 0.0f);
    }
    if (j < jend) {
        int sA = d_asrc[j];
        const float4* p = ((const float4*)d_eap) + (size_t)j * 4;
        float4 a0 = p[0], a1 = p[1], a2 = p[2], a3 = p[3];
        float xA1 = d_x[(size_t)sA * 36 + lane];
        float xA2 = d_x[(size_t)sA * 36 + 32 + (lane & 3)];
        ull aA = bp;
        ull sp;
        sp = pack2(a0.x, a0.x); aA = fma2(sp, Wp[0],  aA);
        sp = pack2(a0.y, a0.y); aA = fma2(sp, Wp[1],  aA);
        sp = pack2(a0.z, a0.z); aA = fma2(sp, Wp[2],  aA);
        sp = pack2(a0.w, a0.w); aA = fma2(sp, Wp[3],  aA);
        sp = pack2(a1.x, a1.x); aA = fma2(sp, Wp[4],  aA);
        sp = pack2(a1.y, a1.y); aA = fma2(sp, Wp[5],  aA);
        sp = pack2(a1.z, a1.z); aA = fma2(sp, Wp[6],  aA);
        sp = pack2(a1.w, a1.w); aA = fma2(sp, Wp[7],  aA);
        sp = pack2(a2.x, a2.x); aA = fma2(sp, Wp[8],  aA);
        sp = pack2(a2.y, a2.y); aA = fma2(sp, Wp[9],  aA);
        sp = pack2(a2.z, a2.z); aA = fma2(sp, Wp[10], aA);
        sp = pack2(a2.w, a2.w); aA = fma2(sp, Wp[11], aA);
        sp = pack2(a3.x, a3.x); aA = fma2(sp, Wp[12], aA);
        sp = pack2(a3.y, a3.y); aA = fma2(sp, Wp[13], aA);
        sp = pack2(a3.z, a3.z); aA = fma2(sp, Wp[14], aA);
        sp = pack2(a3.w, a3.w); aA = fma2(sp, Wp[15], aA);
        float rA1, rA2;
        unpack2(aA, rA1, rA2);
        acc1 += fmaxf(xA1 + rA1, 0.0f);
        acc2 += fmaxf(xA2 + rA2, 0.0f);
    }
    d_agg[(size_t)n * 36 + lane] = acc1;
    if (lane < 4) d_agg[(size_t)n * 36 + 32 + lane] = acc2;
}

// ---------------- GINE2 (CSR): warp per dst, 2-edge unroll, packed FMA2 ----------------
__global__ __launch_bounds__(256, 2) void k_gine2_csr(const float* __restrict__ W, const float* __restrict__ b) {
    int lane = threadIdx.x & 31;
    int n = (blockIdx.x * 256 + threadIdx.x) >> 5;
    if (n >= N_) return;
    ull Wp0[16], Wp1[16];
#pragma unroll
    for (int k = 0; k < 16; k++) {
        float4 w = ((const float4*)W)[k * 32 + lane];
        Wp0[k] = pack2(w.x, w.y);
        Wp1[k] = pack2(w.z, w.w);
    }
    float4 bv = ((const float4*)b)[lane];
    ull bp0 = pack2(bv.x, bv.y), bp1 = pack2(bv.z, bv.w);

    float4 acc = make_float4(0, 0, 0, 0);
    int j = d_off[n], jend = d_off[n + 1];
    for (; j + 1 < jend; j += 2) {
        int sA = d_asrc[j], sB = d_asrc[j + 1];
        const float4* p = ((const float4*)d_eap) + (size_t)j * 4;
        float4 a0 = p[0], a1 = p[1], a2 = p[2], a3 = p[3];
        float4 c0 = p[4], c1 = p[5], c2 = p[6], c3 = p[7];
        float4 hA = ((const float4*)d_h)[(size_t)sA * 32 + lane];
        float4 hB = ((const float4*)d_h)[(size_t)sB * 32 + lane];
        ull A0 = bp0, A1 = bp1;
        ACC2x16(A0, A1, a0, a1, a2, a3);
        ull B0 = bp0, B1 = bp1;
        ACC2x16(B0, B1, c0, c1, c2, c3);
        float rx, ry, rz, rw;
        unpack2(A0, rx, ry); unpack2(A1, rz, rw);
        acc.x += fmaxf(hA.x + rx, 0.0f); acc.y += fmaxf(hA.y + ry, 0.0f);
        acc.z += fmaxf(hA.z + rz, 0.0f); acc.w += fmaxf(hA.w + rw, 0.0f);
        unpack2(B0, rx, ry); unpack2(B1, rz, rw);
        acc.x += fmaxf(hB.x + rx, 0.0f); acc.y += fmaxf(hB.y + ry, 0.0f);
        acc.z += fmaxf(hB.z + rz, 0.0f); acc.w += fmaxf(hB.w + rw, 0.0f);
    }
    if (j < jend) {
        int sA = d_asrc[j];
        const float4* p = ((const float4*)d_eap) + (size_t)j * 4;
        float4 a0 = p[0], a1 = p[1], a2 = p[2], a3 = p[3];
        float4 hA = ((const float4*)d_h)[(size_t)sA * 32 + lane];
        ull A0 = bp0, A1 = bp1;
        ACC2x16(A0, A1, a0, a1, a2, a3);
        float rx, ry, rz, rw;
        unpack2(A0, rx, ry); unpack2(A1, rz, rw);
        acc.x += fmaxf(hA.x + rx, 0.0f); acc.y += fmaxf(hA.y + ry, 0.0f);
        acc.z += fmaxf(hA.z + rz, 0.0f); acc.w += fmaxf(hA.w + rw, 0.0f);
    }
    ((float4*)d_agg)[(size_t)n * 32 + lane] = acc;
}

// ---------------- node MLP: 4 rows/thread, k-blocked x4, float4 staging ----------------
template <int K, bool HASAGG, bool HASBN>
__global__ __launch_bounds__(256) void k_mlp(
    const float* __restrict__ xin, const float* __restrict__ agg,
    const float* __restrict__ epsp,
    const float* __restrict__ W, const float* __restrict__ bias,
    const float* __restrict__ bng, const float* __restrict__ bnb,
    const float* __restrict__ bnm, const float* __restrict__ bnv,
    float* __restrict__ out)
{
    constexpr int TS = (K == 36) ? 40 : K;     // padded row stride for float4 alignment
    constexpr int K4 = K / 4;                  // float4s per input row
    extern __shared__ float sm[];
    float* Ws  = sm;             // K*128
    float* tin = sm + K * 128;   // 32*TS
    int tid = threadIdx.x;
    int lane = tid & 31, w = tid >> 5;
    for (int i = tid; i < K * 32; i += 256) ((float4*)Ws)[i] = ((const float4*)W)[i];
    int c = lane * 4;
    float4 bv = *(const float4*)(bias + c);
    float4 scale = make_float4(1,1,1,1), shift = make_float4(0,0,0,0);
    if (HASBN) {
        float s0 = bng[c+0] * rsqrtf(bnv[c+0] + 1e-5f);
        float s1 = bng[c+1] * rsqrtf(bnv[c+1] + 1e-5f);
        float s2 = bng[c+2] * rsqrtf(bnv[c+2] + 1e-5f);
        float s3 = bng[c+3] * rsqrtf(bnv[c+3] + 1e-5f);
        scale = make_float4(s0, s1, s2, s3);
        shift = make_float4(bnb[c+0] - bnm[c+0]*s0, bnb[c+1] - bnm[c+1]*s1,
                            bnb[c+2] - bnm[c+2]*s2, bnb[c+3] - bnm[c+3]*s3);
    }
    float sx = HASAGG ? (1.0f + *epsp) : 1.0f;
    __syncthreads();

    for (int base = blockIdx.x * 32; base < N_; base += gridDim.x * 32) {
        for (int i = tid; i < 32 * K4; i += 256) {
            int r = i / K4, k4 = i - r * K4;
            int n = base + r;
            if (n < N_) {
                float4 v = *(const float4*)(xin + (size_t)n * K + k4 * 4);
                v.x *= sx; v.y *= sx; v.z *= sx; v.w *= sx;
                if (HASAGG) {
                    float4 g = *(const float4*)(agg + (size_t)n * K + k4 * 4);
                    v.x += g.x; v.y += g.y; v.z += g.z; v.w += g.w;
                }
                *(float4*)(tin + r * TS + k4 * 4) = v;
            }
        }
        __syncthreads();
        const float* t0 = tin + (w * 4) * TS;
        float4 a0 = bv, a1 = bv, a2 = bv, a3 = bv;
#pragma unroll
        for (int k4 = 0; k4 < K; k4 += 4) {
            float4 w0 = *(const float4*)(Ws + (k4+0) * 128 + c);
            float4 w1 = *(const float4*)(Ws + (k4+1) * 128 + c);
            float4 w2 = *(const float4*)(Ws + (k4+2) * 128 + c);
            float4 w3 = *(const float4*)(Ws + (k4+3) * 128 + c);
            float4 t;
            t = *(const float4*)(t0 + 0 * TS + k4);
            FMA4(a0, t.x, w0); FMA4(a0, t.y, w1); FMA4(a0, t.z, w2); FMA4(a0, t.w, w3);
            t = *(const float4*)(t0 + 1 * TS + k4);
            FMA4(a1, t.x, w0); FMA4(a1, t.y, w1); FMA4(a1, t.z, w2); FMA4(a1, t.w, w3);
            t = *(const float4*)(t0 + 2 * TS + k4);
            FMA4(a2, t.x, w0); FMA4(a2, t.y, w1); FMA4(a2, t.z, w2); FMA4(a2, t.w, w3);
            t = *(const float4*)(t0 + 3 * TS + k4);
            FMA4(a3, t.x, w0); FMA4(a3, t.y, w1); FMA4(a3, t.z, w2); FMA4(a3, t.w, w3);
        }
        if (HASBN) {
            a0.x = fmaxf(a0.x,0.f)*scale.x+shift.x; a0.y = fmaxf(a0.y,0.f)*scale.y+shift.y;
            a0.z = fmaxf(a0.z,0.f)*scale.z+shift.z; a0.w = fmaxf(a0.w,0.f)*scale.w+shift.w;
            a1.x = fmaxf(a1.x,0.f)*scale.x+shift.x; a1.y = fmaxf(a1.y,0.f)*scale.y+shift.y;
            a1.z = fmaxf(a1.z,0.f)*scale.z+shift.z; a1.w = fmaxf(a1.w,0.f)*scale.w+shift.w;
            a2.x = fmaxf(a2.x,0.f)*scale.x+shift.x; a2.y = fmaxf(a2.y,0.f)*scale.y+shift.y;
            a2.z = fmaxf(a2.z,0.f)*scale.z+shift.z; a2.w = fmaxf(a2.w,0.f)*scale.w+shift.w;
            a3.x = fmaxf(a3.x,0.f)*scale.x+shift.x; a3.y = fmaxf(a3.y,0.f)*scale.y+shift.y;
            a3.z = fmaxf(a3.z,0.f)*scale.z+shift.z; a3.w = fmaxf(a3.w,0.f)*scale.w+shift.w;
        }
        int n0 = base + w * 4;
        if (n0 + 0 < N_) *(float4*)(out + (size_t)(n0+0) * 128 + c) = a0;
        if (n0 + 1 < N_) *(float4*)(out + (size_t)(n0+1) * 128 + c) = a1;
        if (n0 + 2 < N_) *(float4*)(out + (size_t)(n0+2) * 128 + c) = a2;
        if (n0 + 3 < N_) *(float4*)(out + (size_t)(n0+3) * 128 + c) = a3;
        __syncthreads();
    }
}

// ---------------- GATv2 (CSR): warp per dst, 2-edge unroll, fused softmax ----------------
__global__ __launch_bounds__(256, 2) void k_gat_csr(const float* __restrict__ Wg, const float* __restrict__ attv,
                                                    const float* __restrict__ bias, float* __restrict__ out) {
    int lane = threadIdx.x & 31;
    int n = (blockIdx.x * 256 + threadIdx.x) >> 5;
    if (n >= N_) return;
    ull Wp0[16], Wp1[16];
#pragma unroll
    for (int k = 0; k < 16; k++) {
        float4 w = ((const float4*)Wg)[k * 32 + lane];
        Wp0[k] = pack2(w.x, w.y);
        Wp1[k] = pack2(w.z, w.w);
    }
    float4 av = ((const float4*)attv)[lane];
    float4 bias4 = ((const float4*)bias)[lane & 15];

    float4 xr_d = ((const float4*)d_xr)[(size_t)n * 32 + lane];
    float4 xl_d = ((const float4*)d_xl)[(size_t)n * 32 + lane];
    float4 eeL  = ((const float4*)d_eeL)[lane];

    float4 acc = make_float4(0, 0, 0, 0);
    float den = 0.0f;

    int j = d_off[n], jend = d_off[n + 1];
    for (; j + 1 < jend; j += 2) {
        int sA = d_asrc[j], sB = d_asrc[j + 1];
        const float4* p = ((const float4*)d_eap) + (size_t)j * 4;
        float4 a0 = p[0], a1 = p[1], a2 = p[2], a3 = p[3];
        float4 c0 = p[4], c1 = p[5], c2 = p[6], c3 = p[7];
        float4 xlA = ((const float4*)d_xl)[(size_t)sA * 32 + lane];
        float4 xlB = ((const float4*)d_xl)[(size_t)sB * 32 + lane];
        ull A0 = 0, A1 = 0;
        ACC2x16(A0, A1, a0, a1, a2, a3);
        ull B0 = 0, B1 = 0;
        ACC2x16(B0, B1, c0, c1, c2, c3);
        float rx, ry, rz, rw;
        unpack2(A0, rx, ry); unpack2(A1, rz, rw);
        float qA = lrelu(xlA.x + xr_d.x + rx) * av.x
                 + lrelu(xlA.y + xr_d.y + ry) * av.y
                 + lrelu(xlA.z + xr_d.z + rz) * av.z
                 + lrelu(xlA.w + xr_d.w + rw) * av.w;
        unpack2(B0, rx, ry); unpack2(B1, rz, rw);
        float qB = lrelu(xlB.x + xr_d.x + rx) * av.x
                 + lrelu(xlB.y + xr_d.y + ry) * av.y
                 + lrelu(xlB.z + xr_d.z + rz) * av.z
                 + lrelu(xlB.w + xr_d.w + rw) * av.w;
        qA += __shfl_xor_sync(0xffffffffu, qA, 1);
        qB += __shfl_xor_sync(0xffffffffu, qB, 1);
        qA += __shfl_xor_sync(0xffffffffu, qA, 2);
        qB += __shfl_xor_sync(0xffffffffu, qB, 2);
        qA += __shfl_xor_sync(0xffffffffu, qA, 4);
        qB += __shfl_xor_sync(0xffffffffu, qB, 4);
        qA += __shfl_xor_sync(0xffffffffu, qA, 8);
        qB += __shfl_xor_sync(0xffffffffu, qB, 8);
        float exA = __expf(qA), exB = __expf(qB);
        acc.x += exA * xlA.x + exB * xlB.x;
        acc.y += exA * xlA.y + exB * xlB.y;
        acc.z += exA * xlA.z + exB * xlB.z;
        acc.w += exA * xlA.w + exB * xlB.w;
        den += exA + exB;
    }
    if (j < jend) {
        int sA = d_asrc[j];
        const float4* p = ((const float4*)d_eap) + (size_t)j * 4;
        float4 a0 = p[0], a1 = p[1], a2 = p[2], a3 = p[3];
        float4 xlA = ((const float4*)d_xl)[(size_t)sA * 32 + lane];
        ull A0 = 0, A1 = 0;
        ACC2x16(A0, A1, a0, a1, a2, a3);
        float rx, ry, rz, rw;
        unpack2(A0, rx, ry); unpack2(A1, rz, rw);
        float qA = lrelu(xlA.x + xr_d.x + rx) * av.x
                 + lrelu(xlA.y + xr_d.y + ry) * av.y
                 + lrelu(xlA.z + xr_d.z + rz) * av.z
                 + lrelu(xlA.w + xr_d.w + rw) * av.w;
        qA += __shfl_xor_sync(0xffffffffu, qA, 1);
        qA += __shfl_xor_sync(0xffffffffu, qA, 2);
        qA += __shfl_xor_sync(0xffffffffu, qA, 4);
        qA += __shfl_xor_sync(0xffffffffu, qA, 8);
        float exA = __expf(qA);
        acc.x += exA * xlA.x; acc.y += exA * xlA.y;
        acc.z += exA * xlA.z; acc.w += exA * xlA.w;
        den += exA;
    }

    // self-loop (edge attr = mean of ea -> eeL)
    {
        float q = lrelu(xl_d.x + xr_d.x + eeL.x) * av.x
                + lrelu(xl_d.y + xr_d.y + eeL.y) * av.y
                + lrelu(xl_d.z + xr_d.z + eeL.z) * av.z
                + lrelu(xl_d.w + xr_d.w + eeL.w) * av.w;
        q += __shfl_xor_sync(0xffffffffu, q, 1);
        q += __shfl_xor_sync(0xffffffffu, q, 2);
        q += __shfl_xor_sync(0xffffffffu, q, 4);
        q += __shfl_xor_sync(0xffffffffu, q, 8);
        float ex = __expf(q);
        acc.x += ex * xl_d.x; acc.y += ex * xl_d.y;
        acc.z += ex * xl_d.z; acc.w += ex * xl_d.w;
        den += ex;
    }

    // head mean: lanes 0-15 hold head0 channels, lanes 16-31 hold head1
    float4 accP;
    accP.x = __shfl_xor_sync(0xffffffffu, acc.x, 16);
    accP.y = __shfl_xor_sync(0xffffffffu, acc.y, 16);
    accP.z = __shfl_xor_sync(0xffffffffu, acc.z, 16);
    accP.w = __shfl_xor_sync(0xffffffffu, acc.w, 16);
    float denP = __shfl_xor_sync(0xffffffffu, den, 16);
    if (lane < 16) {
        float inv = 0.5f / den, invP = 0.5f / denP;
        float4 o;
        o.x = acc.x * inv + accP.x * invP + bias4.x;
        o.y = acc.y * inv + accP.y * invP + bias4.y;
        o.z = acc.z * inv + accP.z * invP + bias4.z;
        o.w = acc.w * inv + accP.w * invP + bias4.w;
        ((float4*)out)[(size_t)n * 16 + lane] = o;
    }
}

// ---------------- launch ----------------
extern "C" void kernel_launch(void* const* d_in, const int* in_sizes, int n_in,
                              void* d_out, int out_size) {
    const int*   x_cat    = (const int*)  d_in[0];
    const float* x_cont   = (const float*)d_in[1];
    const int*   e_cat    = (const int*)  d_in[2];
    const float* e_cont   = (const float*)d_in[3];
    const int*   eidx     = (const int*)  d_in[4];
    const int*   src = eidx;
    const int*   dst = eidx + E_;
    const float* node_emb = (const float*)d_in[5];
    const float* edge_emb = (const float*)d_in[6];
    const float* eps1     = (const float*)d_in[7];
    const float* W1e      = (const float*)d_in[8];
    const float* b1e      = (const float*)d_in[9];
    const float* nnW1     = (const float*)d_in[10];
    const float* nnb1     = (const float*)d_in[11];
    const float* g1 = (const float*)d_in[12], *bb1 = (const float*)d_in[13];
    const float* m1 = (const float*)d_in[14], *v1  = (const float*)d_in[15];
    const float* eps2     = (const float*)d_in[16];
    const float* W2e      = (const float*)d_in[17];
    const float* b2e      = (const float*)d_in[18];
    const float* nnW2     = (const float*)d_in[19];
    const float* nnb2     = (const float*)d_in[20];
    const float* g2 = (const float*)d_in[21], *bb2 = (const float*)d_in[22];
    const float* m2 = (const float*)d_in[23], *v2  = (const float*)d_in[24];
    const float* Wl  = (const float*)d_in[25], *bl = (const float*)d_in[26];
    const float* Wr  = (const float*)d_in[27], *br = (const float*)d_in[28];
    const float* Weg = (const float*)d_in[29];
    const float* att = (const float*)d_in[30];
    const float* gbias = (const float*)d_in[31];
    float* out = (float*)d_out;

    void *p_x, *p_agg, *p_h, *p_h2, *p_xl, *p_xr, *p_easum, *p_cnt;
    cudaGetSymbolAddress(&p_x,    d_x);
    cudaGetSymbolAddress(&p_agg,  d_agg);
    cudaGetSymbolAddress(&p_h,    d_h);
    cudaGetSymbolAddress(&p_h2,   d_h2);
    cudaGetSymbolAddress(&p_xl,   d_xl);
    cudaGetSymbolAddress(&p_xr,   d_xr);
    cudaGetSymbolAddress(&p_easum,d_easum);
    cudaGetSymbolAddress(&p_cnt,  d_cnt);

    const int smem36  = (36 * 128 + 32 * 40) * 4;    // 23552
    const int smem128 = (128 * 128 + 32 * 128) * 4;  // 81920
    cudaFuncSetAttribute(k_mlp<128, true,  true >, cudaFuncAttributeMaxDynamicSharedMemorySize, smem128);
    cudaFuncSetAttribute(k_mlp<128, false, false>, cudaFuncAttributeMaxDynamicSharedMemorySize, smem128);

    // init
    cudaMemsetAsync(p_easum, 0, 16 * 4);
    cudaMemsetAsync(p_cnt,   0, N_ * 4);

    // features (+folded easum)
    k_node_feat<<<(N_ * 36 + 255) / 256, 256>>>(x_cat, x_cont, node_emb);
    k_edge_feat<<<(E_ * 16) / 256, 256>>>(e_cat, e_cont, edge_emb);
    k_eeloop<<<1, 128>>>(Weg);

    // CSR build: count -> 3-phase parallel scan -> fill (permutes ea)
    const int nScanBlocks = (N_ + 255) / 256;   // 196
    k_count<<<(E_ + 255) / 256, 256>>>(dst);
    k_scan1<<<nScanBlocks, 256>>>();
    k_scan2<<<1, 256>>>();
    k_scan3<<<nScanBlocks, 256>>>();
    k_fill<<<(E_ + 255) / 256, 256>>>(src, dst);

    const int nodeGrid = (N_ * 32 + 255) / 256;   // warp per node

    // GINE layer 1
    k_gine1_csr<<<nodeGrid, 256>>>(W1e, b1e);
    k_mlp<36, true, true><<<296, 256, smem36>>>(
        (const float*)p_x, (const float*)p_agg, eps1, nnW1, nnb1, g1, bb1, m1, v1, (float*)p_h);

    // GINE layer 2
    k_gine2_csr<<<nodeGrid, 256>>>(W2e, b2e);
    k_mlp<128, true, true><<<296, 256, smem128>>>(
        (const float*)p_h, (const float*)p_agg, eps2, nnW2, nnb2, g2, bb2, m2, v2, (float*)p_h2);

    // GATv2 linear transforms
    k_mlp<128, false, false><<<296, 256, smem128>>>(
        (const float*)p_h2, nullptr, nullptr, Wl, bl, nullptr, nullptr, nullptr, nullptr, (float*)p_xl);
    k_mlp<128, false, false><<<296, 256, smem128>>>(
        (const float*)p_h2, nullptr, nullptr, Wr, br, nullptr, nullptr, nullptr, nullptr, (float*)p_xr);

    // GATv2 fused attention + output
    k_gat_csr<<<nodeGrid, 256>>>(Weg, att, gbias, out);
}